// round 7
// baseline (speedup 1.0000x reference)
#include <cuda_runtime.h>
#include <cstdint>

// B=8, C=16, H=512, W=512, M=N=15
//   K:     [128, 16, 16]  f32
//   basis: [262144, 16, 16] f32, separable: basis[h*W+w,p,q] = Bu[h,p]*Bv[w,q]
//   out:   [128, 512, 512] f32
//
// Bu[h,p] = sum_q basis[h*W, p, q]; Bv[w,q] = sum_p basis[w, p, q]
// T[bc,p,w] = sum_q K[bc,p,q]*Bv[w,q];  out[bc,h,w] = sum_p Bu[h,p]*T[bc,p,w]

#define HH 512
#define WW 512
#define PP 16
#define QQ 16
#define BC 128
#define ROWS 128

__device__ unsigned long long g_Bu2[PP * HH];  // dup'd Bu: [p][h] = (b,b), 64 KB
__device__ float g_BvT[QQ * WW];               // Bv transposed: [q][w], 32 KB

__device__ __forceinline__ unsigned long long pk(float a, float b) {
    unsigned long long r;
    asm("mov.b64 %0, {%1, %2};" : "=l"(r) : "f"(a), "f"(b));
    return r;
}
__device__ __forceinline__ void fma2(unsigned long long& d, unsigned long long a,
                                     unsigned long long b) {
    asm("fma.rn.f32x2 %0, %1, %2, %0;" : "+l"(d) : "l"(a), "l"(b));
}
__device__ __forceinline__ void unpk(unsigned long long v, float& a, float& b) {
    asm("mov.b64 {%0, %1}, %2;" : "=f"(a), "=f"(b) : "l"(v));
}

// ---------------------------------------------------------------------------
// Kernel A: extraction only. Warp-per-row, coalesced loads, shfl reductions.
//   blocks 0..63 : Bu rows (h = 8*blk + warp) -> g_Bu2 dup'd
//   blocks 64..127: Bv rows (w = 8*(blk-64) + warp) -> g_BvT
// ---------------------------------------------------------------------------
__global__ __launch_bounds__(256) void extract_factors(const float* __restrict__ basis) {
    int warp = threadIdx.x >> 5, lane = threadIdx.x & 31;
    if (blockIdx.x < 64) {
        int h = blockIdx.x * 8 + warp;
        const float4* r4 = reinterpret_cast<const float4*>(basis + (size_t)h * WW * (PP * QQ));
        float4 a = r4[lane * 2];
        float4 b = r4[lane * 2 + 1];
        float s = (a.x + a.y) + (a.z + a.w) + (b.x + b.y) + (b.z + b.w);
        s += __shfl_xor_sync(0xffffffffu, s, 1);   // lanes (2k,2k+1) cover p=k
        if ((lane & 1) == 0) g_Bu2[(lane >> 1) * HH + h] = pk(s, s);
    } else {
        int w = (blockIdx.x - 64) * 8 + warp;
        const float4* r4 = reinterpret_cast<const float4*>(basis + (size_t)w * (PP * QQ));
        float4 a = r4[lane * 2];
        float4 b = r4[lane * 2 + 1];
        // lane l: p = l>>1, q = (l&1)*8 + j; butterfly over p (offsets 2..16)
        #pragma unroll
        for (int off = 2; off <= 16; off <<= 1) {
            a.x += __shfl_xor_sync(0xffffffffu, a.x, off);
            a.y += __shfl_xor_sync(0xffffffffu, a.y, off);
            a.z += __shfl_xor_sync(0xffffffffu, a.z, off);
            a.w += __shfl_xor_sync(0xffffffffu, a.w, off);
            b.x += __shfl_xor_sync(0xffffffffu, b.x, off);
            b.y += __shfl_xor_sync(0xffffffffu, b.y, off);
            b.z += __shfl_xor_sync(0xffffffffu, b.z, off);
            b.w += __shfl_xor_sync(0xffffffffu, b.w, off);
        }
        if (lane < 2) {
            int q0 = lane * 8;
            g_BvT[(q0 + 0) * WW + w] = a.x;
            g_BvT[(q0 + 1) * WW + w] = a.y;
            g_BvT[(q0 + 2) * WW + w] = a.z;
            g_BvT[(q0 + 3) * WW + w] = a.w;
            g_BvT[(q0 + 4) * WW + w] = b.x;
            g_BvT[(q0 + 5) * WW + w] = b.y;
            g_BvT[(q0 + 6) * WW + w] = b.z;
            g_BvT[(q0 + 7) * WW + w] = b.w;
        }
    }
}

// ---------------------------------------------------------------------------
// Kernel B (fused, w-packed accumulators):
//   grid (H/ROWS=4, BC), 128 threads; thread t owns w = 4t..4t+3.
//   Prologue: T[p] as NATURAL pairs Txy/Tzw (64 regs, no dup, no spill),
//             computed from g_BvT (coalesced LDG.128) x dup'd K (LDS.64 bcast).
//   Main loop: per p, 2 broadcast LDS.128 of dup'd Bu (4 h-rows) + 8 FFMA2.
//   Stores: natural float4 per row.
// ---------------------------------------------------------------------------
__global__ __launch_bounds__(128) void fused_stage(const float* __restrict__ K,
                                                   float* __restrict__ out) {
    int bc = blockIdx.y;
    int h0 = blockIdx.x * ROWS;
    int t = threadIdx.x;

    __shared__ unsigned long long sK2[PP * QQ];      // dup'd (k,k), 2 KB
    __shared__ unsigned long long sBu2[PP * ROWS];   // dup'd (b,b), 16 KB

    // Stage K[bc] duplicated
    {
        float k0 = K[(size_t)bc * (PP * QQ) + t];
        float k1 = K[(size_t)bc * (PP * QQ) + t + 128];
        sK2[t] = pk(k0, k0);
        sK2[t + 128] = pk(k1, k1);
    }
    // Stage dup'd Bu tile: coalesced ulonglong2 copy
    {
        ulonglong2* dst = reinterpret_cast<ulonglong2*>(sBu2);
        #pragma unroll
        for (int i = t; i < PP * ROWS / 2; i += 128) {
            int p = i >> 6, c = i & 63;
            dst[i] = *reinterpret_cast<const ulonglong2*>(&g_Bu2[p * HH + h0 + 2 * c]);
        }
    }
    __syncthreads();

    // Prologue: T[p][w0..w3] as natural pairs, streaming over q
    unsigned long long Txy[PP], Tzw[PP];
    #pragma unroll
    for (int p = 0; p < PP; ++p) { Txy[p] = 0ull; Tzw[p] = 0ull; }
    {
        const float4* bvt4 = reinterpret_cast<const float4*>(g_BvT);
        #pragma unroll
        for (int q = 0; q < QQ; ++q) {
            float4 v = bvt4[q * (WW / 4) + t];     // coalesced LDG.128
            unsigned long long vxy = pk(v.x, v.y);
            unsigned long long vzw = pk(v.z, v.w);
            #pragma unroll
            for (int p = 0; p < PP; ++p) {
                unsigned long long kk = sK2[p * QQ + q];   // LDS.64 broadcast
                fma2(Txy[p], kk, vxy);
                fma2(Tzw[p], kk, vzw);
            }
        }
    }

    float* obase = out + (size_t)bc * HH * WW + (size_t)h0 * WW + 4 * t;

    #pragma unroll 2
    for (int g = 0; g < ROWS; g += 4) {
        unsigned long long axy[4], azw[4];
        #pragma unroll
        for (int r = 0; r < 4; ++r) { axy[r] = 0ull; azw[r] = 0ull; }

        #pragma unroll
        for (int p = 0; p < PP; ++p) {
            // dup'd Bu rows g..g+3: 2 broadcast LDS.128
            ulonglong2 b01 = *reinterpret_cast<const ulonglong2*>(&sBu2[p * ROWS + g]);
            ulonglong2 b23 = *reinterpret_cast<const ulonglong2*>(&sBu2[p * ROWS + g + 2]);
            fma2(axy[0], b01.x, Txy[p]); fma2(azw[0], b01.x, Tzw[p]);
            fma2(axy[1], b01.y, Txy[p]); fma2(azw[1], b01.y, Tzw[p]);
            fma2(axy[2], b23.x, Txy[p]); fma2(azw[2], b23.x, Tzw[p]);
            fma2(axy[3], b23.y, Txy[p]); fma2(azw[3], b23.y, Tzw[p]);
        }

        #pragma unroll
        for (int r = 0; r < 4; ++r) {
            float x, y, z, w;
            unpk(axy[r], x, y);
            unpk(azw[r], z, w);
            __stcs(reinterpret_cast<float4*>(obase + (size_t)(g + r) * WW),
                   make_float4(x, y, z, w));
        }
    }
}

// ---------------------------------------------------------------------------
extern "C" void kernel_launch(void* const* d_in, const int* in_sizes, int n_in,
                              void* d_out, int out_size) {
    const float* K     = (const float*)d_in[0];
    const float* basis = (const float*)d_in[1];
    float* out = (float*)d_out;
    (void)in_sizes; (void)n_in; (void)out_size;

    extract_factors<<<128, 256>>>(basis);

    dim3 g2(HH / ROWS, BC);
    fused_stage<<<g2, 128>>>(K, out);
}